// round 1
// baseline (speedup 1.0000x reference)
#include <cuda_runtime.h>
#include <math.h>

// Problem constants
#define BB 8
#define CC 256
#define HH 56
#define WW 56
#define HW (HH*WW)          // 3136
#define KK 3
#define TAPS 9
#define MID 51
#define CKK (CC*TAPS)       // 2304
#define GAIN_OVER_K 0.4714045207910317f   // sqrt(2)/3

// k1 tiling
#define K1_BLK 128
#define K1_TILES 25          // ceil(3136/128)

// Scratch (device globals; no allocation in kernel_launch)
__device__ float g_pp[BB * K1_TILES * CC];   // partial pooled sums
__device__ float g_sf[BB * TAPS * HW];       // normalized spatial filter
__device__ float g_cf[BB * CKK];             // channel filter

// ---------------------------------------------------------------------------
// Kernel 1: one pass over x.
//  - sf[b,n,pix] = normalize_n( sum_c x[b,c,pix]*ws[n,c] + bs[n] ) * (sqrt2/3)
//  - partial pooled sums per (b, tile, c) via deterministic warp reduction
// ---------------------------------------------------------------------------
__global__ void __launch_bounds__(K1_BLK) k1_sf_pool(
    const float* __restrict__ x,
    const float* __restrict__ ws,
    const float* __restrict__ bs)
{
    __shared__ float ws_s[TAPS * CC];        // 9*256 = 9 KB
    __shared__ float psum[CC * 4];           // [c][warp], 4 warps

    const int b    = blockIdx.y;
    const int tile = blockIdx.x;
    const int tid  = threadIdx.x;
    const int warp = tid >> 5;
    const int lane = tid & 31;

    for (int i = tid; i < TAPS * CC; i += K1_BLK) ws_s[i] = ws[i];
    __syncthreads();

    const int pix   = tile * K1_BLK + tid;
    const bool valid = (pix < HW);
    const float* xb = x + (size_t)b * CC * HW;

    float acc[TAPS];
#pragma unroll
    for (int n = 0; n < TAPS; n++) acc[n] = 0.f;

    for (int c = 0; c < CC; c++) {
        float xv = valid ? __ldg(xb + c * HW + pix) : 0.f;
#pragma unroll
        for (int n = 0; n < TAPS; n++)
            acc[n] = fmaf(xv, ws_s[n * CC + c], acc[n]);
        // deterministic warp-sum of xv -> pooled partials
        float s = xv;
#pragma unroll
        for (int o = 16; o > 0; o >>= 1) s += __shfl_down_sync(0xffffffffu, s, o);
        if (lane == 0) psum[c * 4 + warp] = s;
    }
    __syncthreads();

    // thread tid handles channels tid, tid+128 (blockDim=128, C=256)
    for (int c = tid; c < CC; c += K1_BLK) {
        float s = psum[c * 4 + 0] + psum[c * 4 + 1] + psum[c * 4 + 2] + psum[c * 4 + 3];
        g_pp[(b * K1_TILES + tile) * CC + c] = s;
    }

    if (valid) {
        float m = 0.f;
#pragma unroll
        for (int n = 0; n < TAPS; n++) { acc[n] += __ldg(bs + n); m += acc[n]; }
        m *= (1.f / 9.f);
        float ss = 0.f;
#pragma unroll
        for (int n = 0; n < TAPS; n++) { float d = acc[n] - m; ss = fmaf(d, d, ss); }
        float inv = GAIN_OVER_K / (sqrtf(ss * (1.f / 8.f)) + 1e-10f);
#pragma unroll
        for (int n = 0; n < TAPS; n++)
            g_sf[((size_t)b * TAPS + n) * HW + pix] = (acc[n] - m) * inv;
    }
}

// ---------------------------------------------------------------------------
// Kernel 2: pooled mean -> MLP (256->51 relu ->2304) -> per-channel-9
// normalize -> * fn_std = cf.   One block per batch element.
// ---------------------------------------------------------------------------
__global__ void __launch_bounds__(256) k2_mlp_cf(
    const float* __restrict__ w1, const float* __restrict__ b1,
    const float* __restrict__ w2, const float* __restrict__ b2,
    const float* __restrict__ fn_std)
{
    __shared__ float pooled_s[CC];
    __shared__ float y1_s[MID];

    const int b   = blockIdx.x;
    const int tid = threadIdx.x;

    // finish pooled mean
    float s = 0.f;
#pragma unroll
    for (int t = 0; t < K1_TILES; t++) s += g_pp[(b * K1_TILES + t) * CC + tid];
    pooled_s[tid] = s * (1.f / (float)HW);
    __syncthreads();

    // layer 1: 51 outputs, relu
    if (tid < MID) {
        float a = __ldg(b1 + tid);
        const float* wr = w1 + tid * CC;
        for (int c = 0; c < CC; c++) a = fmaf(pooled_s[c], __ldg(wr + c), a);
        y1_s[tid] = fmaxf(a, 0.f);
    }
    __syncthreads();

    // layer 2: thread tid = channel c, computes its 9 taps
    const int c = tid;
    float y[TAPS];
#pragma unroll
    for (int k = 0; k < TAPS; k++) {
        const float* wr = w2 + (size_t)(c * TAPS + k) * MID;
        float a = __ldg(b2 + c * TAPS + k);
        for (int m = 0; m < MID; m++) a = fmaf(y1_s[m], __ldg(wr + m), a);
        y[k] = a;
    }
    float m = 0.f;
#pragma unroll
    for (int k = 0; k < TAPS; k++) m += y[k];
    m *= (1.f / 9.f);
    float ss = 0.f;
#pragma unroll
    for (int k = 0; k < TAPS; k++) { float d = y[k] - m; ss = fmaf(d, d, ss); }
    float inv = 1.f / (sqrtf(ss * (1.f / 8.f)) + 1e-10f);
#pragma unroll
    for (int k = 0; k < TAPS; k++)
        g_cf[(size_t)b * CKK + c * TAPS + k] =
            (y[k] - m) * inv * __ldg(fn_std + c * TAPS + k);
}

// ---------------------------------------------------------------------------
// Kernel 3: DDF combine.
//   out[b,c,i,j] = sum_{u,v} x[b,c,i+u-1,j+v-1] * cf[b,c,u*3+v] * sf[b,u*3+v,i,j]
// Block = 8x56 spatial tile, 16 channels processed sequentially (sf tile in
// smem reused across channels). Grid (7 row-tiles, 16 channel-groups, 8 b).
// ---------------------------------------------------------------------------
#define K3_CG 16
__global__ void __launch_bounds__(448) k3_ddf(
    const float* __restrict__ x, float* __restrict__ out)
{
    __shared__ float sf_s[TAPS * 8 * WW];   // 9*448 floats = 16128 B
    __shared__ float cf_s[K3_CG * TAPS];    // 144 floats
    __shared__ float xs[10 * 58];           // halo tile, 2320 B

    const int b  = blockIdx.z;
    const int cg = blockIdx.y;
    const int r0 = blockIdx.x * 8;
    const int tx = threadIdx.x;
    const int ty = threadIdx.y;
    const int tid = ty * WW + tx;

#pragma unroll
    for (int n = 0; n < TAPS; n++)
        sf_s[n * 448 + tid] = g_sf[((size_t)b * TAPS + n) * HW + (r0 + ty) * WW + tx];
    if (tid < K3_CG * TAPS)
        cf_s[tid] = g_cf[(size_t)b * CKK + (cg * K3_CG) * TAPS + tid];
    __syncthreads();

    float sfr[TAPS];
#pragma unroll
    for (int n = 0; n < TAPS; n++) sfr[n] = sf_s[n * 448 + tid];

    const float* xb = x + (size_t)b * CC * HW;
    const size_t out_b = (size_t)b * CC * HW;

    for (int g = 0; g < K3_CG; g++) {
        const int c = cg * K3_CG + g;
        __syncthreads();   // previous channel's xs reads complete
        for (int i = tid; i < 10 * 58; i += 448) {
            int rr = i / 58, cc2 = i % 58;
            int gr = r0 - 1 + rr, gc = cc2 - 1;
            float v = 0.f;
            if (gr >= 0 && gr < HH && gc >= 0 && gc < WW)
                v = __ldg(xb + c * HW + gr * WW + gc);
            xs[i] = v;
        }
        __syncthreads();

        float w[TAPS];
#pragma unroll
        for (int t = 0; t < TAPS; t++) w[t] = cf_s[g * TAPS + t] * sfr[t];

        float acc = 0.f;
#pragma unroll
        for (int u = 0; u < KK; u++)
#pragma unroll
            for (int v = 0; v < KK; v++)
                acc = fmaf(xs[(ty + u) * 58 + tx + v], w[u * KK + v], acc);

        out[out_b + (size_t)c * HW + (r0 + ty) * WW + tx] = acc;
    }
}

// ---------------------------------------------------------------------------
extern "C" void kernel_launch(void* const* d_in, const int* in_sizes, int n_in,
                              void* d_out, int out_size)
{
    const float* x      = (const float*)d_in[0];
    const float* w1     = (const float*)d_in[1];
    const float* b1     = (const float*)d_in[2];
    const float* w2     = (const float*)d_in[3];
    const float* b2     = (const float*)d_in[4];
    const float* ws     = (const float*)d_in[5];
    const float* bs     = (const float*)d_in[6];
    const float* fn_std = (const float*)d_in[7];
    float* out = (float*)d_out;

    dim3 g1(K1_TILES, BB);
    k1_sf_pool<<<g1, K1_BLK>>>(x, ws, bs);

    k2_mlp_cf<<<BB, 256>>>(w1, b1, w2, b2, fn_std);

    dim3 g3(HH / 8, CC / K3_CG, BB);
    dim3 b3(WW, 8);
    k3_ddf<<<g3, b3>>>(x, out);
}

// round 2
// speedup vs baseline: 1.3473x; 1.3473x over previous
#include <cuda_runtime.h>
#include <math.h>

// Problem constants
#define BB 8
#define CC 256
#define HH 56
#define WW 56
#define HW (HH*WW)          // 3136
#define KK 3
#define TAPS 9
#define MID 51
#define CKK (CC*TAPS)       // 2304
#define GAIN_OVER_K 0.4714045207910317f   // sqrt(2)/3

// Scratch (device globals; no allocation in kernel_launch)
__device__ float g_pooled[BB * CC];          // pooled means
__device__ float g_sf[BB * TAPS * HW];       // normalized spatial filter
__device__ float g_cf[BB * CKK];             // channel filter

// ---------------------------------------------------------------------------
// Kernel 0: pooled[b,c] = mean over HW of x[b,c,:,:]
// One block per (c,b). Coalesced float4 reduction. x lives in L2 -> cheap.
// ---------------------------------------------------------------------------
__global__ void __launch_bounds__(128) k0_pool(const float* __restrict__ x)
{
    const int c = blockIdx.x;
    const int b = blockIdx.y;
    const int tid  = threadIdx.x;
    const int warp = tid >> 5;
    const int lane = tid & 31;

    const float4* p4 = (const float4*)(x + ((size_t)b * CC + c) * HW);
    float s = 0.f;
    // HW/4 = 784 float4 elements
#pragma unroll
    for (int i = tid; i < 784; i += 128) {
        float4 v = __ldg(p4 + i);
        s += (v.x + v.y) + (v.z + v.w);
    }
#pragma unroll
    for (int o = 16; o > 0; o >>= 1) s += __shfl_down_sync(0xffffffffu, s, o);

    __shared__ float ws4[4];
    if (lane == 0) ws4[warp] = s;
    __syncthreads();
    if (tid == 0)
        g_pooled[b * CC + c] = (ws4[0] + ws4[1] + ws4[2] + ws4[3]) * (1.f / (float)HW);
}

// ---------------------------------------------------------------------------
// Kernel 1: spatial filter.
//  sf[b,n,pix] = normalize_n( sum_c x[b,c,pix]*ws[n,c] + bs[n] ) * (sqrt2/3)
// Block: 64 pixels x 4 channel-groups (256 thr). Each thread accumulates
// acc[9] over 64 channels; groups combined in smem; 64 threads normalize.
// ---------------------------------------------------------------------------
#define P1 64
#define G1 4
__global__ void __launch_bounds__(256) k1_sf(
    const float* __restrict__ x,
    const float* __restrict__ ws,
    const float* __restrict__ bs)
{
    __shared__ float ws_s[TAPS * CC];           // 9 KB
    __shared__ float red[G1 * TAPS * P1];       // 9 KB  [(g*9+n)*64+p]

    const int b     = blockIdx.y;
    const int tilep = blockIdx.x;
    const int tid   = threadIdx.x;
    const int p     = tid & (P1 - 1);
    const int g     = tid >> 6;

    for (int i = tid; i < TAPS * CC; i += 256) ws_s[i] = ws[i];
    __syncthreads();

    const int pix   = tilep * P1 + p;
    const bool valid = (pix < HW);
    const float* xb = x + (size_t)b * CC * HW + (size_t)g * 64 * HW;

    float acc[TAPS];
#pragma unroll
    for (int n = 0; n < TAPS; n++) acc[n] = 0.f;

#pragma unroll 4
    for (int cc = 0; cc < 64; cc++) {
        float xv = valid ? __ldg(xb + (size_t)cc * HW + pix) : 0.f;
        const float* wsc = ws_s + (g * 64 + cc);
#pragma unroll
        for (int n = 0; n < TAPS; n++)
            acc[n] = fmaf(xv, wsc[n * CC], acc[n]);
    }

#pragma unroll
    for (int n = 0; n < TAPS; n++) red[(g * TAPS + n) * P1 + p] = acc[n];
    __syncthreads();

    if (tid < P1) {
        const int pix2 = tilep * P1 + tid;
        if (pix2 < HW) {
            float a[TAPS];
            float m = 0.f;
#pragma unroll
            for (int n = 0; n < TAPS; n++) {
                a[n] = red[(0 * TAPS + n) * P1 + tid]
                     + red[(1 * TAPS + n) * P1 + tid]
                     + red[(2 * TAPS + n) * P1 + tid]
                     + red[(3 * TAPS + n) * P1 + tid]
                     + __ldg(bs + n);
                m += a[n];
            }
            m *= (1.f / 9.f);
            float ss = 0.f;
#pragma unroll
            for (int n = 0; n < TAPS; n++) { float d = a[n] - m; ss = fmaf(d, d, ss); }
            float inv = GAIN_OVER_K / (sqrtf(ss * (1.f / 8.f)) + 1e-10f);
#pragma unroll
            for (int n = 0; n < TAPS; n++)
                g_sf[((size_t)b * TAPS + n) * HW + pix2] = (a[n] - m) * inv;
        }
    }
}

// ---------------------------------------------------------------------------
// Kernel 2: MLP (256->51 relu ->2304) -> per-channel-9 normalize -> * fn_std
// One block per batch element.
// ---------------------------------------------------------------------------
__global__ void __launch_bounds__(256) k2_mlp_cf(
    const float* __restrict__ w1, const float* __restrict__ b1,
    const float* __restrict__ w2, const float* __restrict__ b2,
    const float* __restrict__ fn_std)
{
    __shared__ float pooled_s[CC];
    __shared__ float y1_s[MID];

    const int b   = blockIdx.x;
    const int tid = threadIdx.x;

    pooled_s[tid] = g_pooled[b * CC + tid];
    __syncthreads();

    if (tid < MID) {
        float a = __ldg(b1 + tid);
        const float* wr = w1 + tid * CC;
        for (int c = 0; c < CC; c++) a = fmaf(pooled_s[c], __ldg(wr + c), a);
        y1_s[tid] = fmaxf(a, 0.f);
    }
    __syncthreads();

    const int c = tid;
    float y[TAPS];
#pragma unroll
    for (int k = 0; k < TAPS; k++) {
        const float* wr = w2 + (size_t)(c * TAPS + k) * MID;
        float a = __ldg(b2 + c * TAPS + k);
        for (int m = 0; m < MID; m++) a = fmaf(y1_s[m], __ldg(wr + m), a);
        y[k] = a;
    }
    float m = 0.f;
#pragma unroll
    for (int k = 0; k < TAPS; k++) m += y[k];
    m *= (1.f / 9.f);
    float ss = 0.f;
#pragma unroll
    for (int k = 0; k < TAPS; k++) { float d = y[k] - m; ss = fmaf(d, d, ss); }
    float inv = 1.f / (sqrtf(ss * (1.f / 8.f)) + 1e-10f);
#pragma unroll
    for (int k = 0; k < TAPS; k++)
        g_cf[(size_t)b * CKK + c * TAPS + k] =
            (y[k] - m) * inv * __ldg(fn_std + c * TAPS + k);
}

// ---------------------------------------------------------------------------
// Kernel 3: DDF combine.
//   out[b,c,i,j] = sum_{u,v} x[b,c,i+u-1,j+v-1] * cf[b,c,u*3+v] * sf[b,u*3+v,i,j]
// Block = 8x56 spatial tile, 16 channels sequentially (sf tile reused).
// ---------------------------------------------------------------------------
#define K3_CG 16
__global__ void __launch_bounds__(448) k3_ddf(
    const float* __restrict__ x, float* __restrict__ out)
{
    __shared__ float sf_s[TAPS * 8 * WW];
    __shared__ float cf_s[K3_CG * TAPS];
    __shared__ float xs[10 * 58];

    const int b  = blockIdx.z;
    const int cg = blockIdx.y;
    const int r0 = blockIdx.x * 8;
    const int tx = threadIdx.x;
    const int ty = threadIdx.y;
    const int tid = ty * WW + tx;

#pragma unroll
    for (int n = 0; n < TAPS; n++)
        sf_s[n * 448 + tid] = g_sf[((size_t)b * TAPS + n) * HW + (r0 + ty) * WW + tx];
    if (tid < K3_CG * TAPS)
        cf_s[tid] = g_cf[(size_t)b * CKK + (cg * K3_CG) * TAPS + tid];
    __syncthreads();

    float sfr[TAPS];
#pragma unroll
    for (int n = 0; n < TAPS; n++) sfr[n] = sf_s[n * 448 + tid];

    const float* xb = x + (size_t)b * CC * HW;
    const size_t out_b = (size_t)b * CC * HW;

    for (int g = 0; g < K3_CG; g++) {
        const int c = cg * K3_CG + g;
        __syncthreads();
        for (int i = tid; i < 10 * 58; i += 448) {
            int rr = i / 58, cc2 = i % 58;
            int gr = r0 - 1 + rr, gc = cc2 - 1;
            float v = 0.f;
            if (gr >= 0 && gr < HH && gc >= 0 && gc < WW)
                v = __ldg(xb + c * HW + gr * WW + gc);
            xs[i] = v;
        }
        __syncthreads();

        float w[TAPS];
#pragma unroll
        for (int t = 0; t < TAPS; t++) w[t] = cf_s[g * TAPS + t] * sfr[t];

        float acc = 0.f;
#pragma unroll
        for (int u = 0; u < KK; u++)
#pragma unroll
            for (int v = 0; v < KK; v++)
                acc = fmaf(xs[(ty + u) * 58 + tx + v], w[u * KK + v], acc);

        out[out_b + (size_t)c * HW + (r0 + ty) * WW + tx] = acc;
    }
}

// ---------------------------------------------------------------------------
extern "C" void kernel_launch(void* const* d_in, const int* in_sizes, int n_in,
                              void* d_out, int out_size)
{
    const float* x      = (const float*)d_in[0];
    const float* w1     = (const float*)d_in[1];
    const float* b1     = (const float*)d_in[2];
    const float* w2     = (const float*)d_in[3];
    const float* b2     = (const float*)d_in[4];
    const float* ws     = (const float*)d_in[5];
    const float* bs     = (const float*)d_in[6];
    const float* fn_std = (const float*)d_in[7];
    float* out = (float*)d_out;

    dim3 g0(CC, BB);
    k0_pool<<<g0, 128>>>(x);

    dim3 g1((HW + P1 - 1) / P1, BB);   // 49 x 8
    k1_sf<<<g1, 256>>>(x, ws, bs);

    k2_mlp_cf<<<BB, 256>>>(w1, b1, w2, b2, fn_std);

    dim3 g3(HH / 8, CC / K3_CG, BB);
    dim3 b3(WW, 8);
    k3_ddf<<<g3, b3>>>(x, out);
}

// round 3
// speedup vs baseline: 2.4021x; 1.7829x over previous
#include <cuda_runtime.h>
#include <math.h>

// Problem constants
#define BB 8
#define CC 256
#define HH 56
#define WW 56
#define HW (HH*WW)          // 3136
#define KK 3
#define TAPS 9
#define MID 51
#define CKK (CC*TAPS)       // 2304
#define GAIN_OVER_K 0.4714045207910317f   // sqrt(2)/3

// Scratch (device globals; no allocation in kernel_launch)
__device__ float g_pooled[BB * CC];
__device__ float g_sf[BB * TAPS * HW];
__device__ float g_cf[BB * CKK];

// ---------------------------------------------------------------------------
// Kernel 0: pooled[b,c] = mean over HW of x[b,c,:,:]
// ---------------------------------------------------------------------------
__global__ void __launch_bounds__(128) k0_pool(const float* __restrict__ x)
{
    const int c = blockIdx.x;
    const int b = blockIdx.y;
    const int tid  = threadIdx.x;
    const int warp = tid >> 5;
    const int lane = tid & 31;

    const float4* p4 = (const float4*)(x + ((size_t)b * CC + c) * HW);
    float s = 0.f;
#pragma unroll
    for (int i = tid; i < 784; i += 128) {
        float4 v = __ldg(p4 + i);
        s += (v.x + v.y) + (v.z + v.w);
    }
#pragma unroll
    for (int o = 16; o > 0; o >>= 1) s += __shfl_down_sync(0xffffffffu, s, o);

    __shared__ float ws4[4];
    if (lane == 0) ws4[warp] = s;
    __syncthreads();
    if (tid == 0)
        g_pooled[b * CC + c] = (ws4[0] + ws4[1] + ws4[2] + ws4[3]) * (1.f / (float)HW);
}

// ---------------------------------------------------------------------------
// Kernel 1: spatial filter. Block: 64 pixels x 4 channel-groups (256 thr).
// ws transposed in smem to [c][12] so per-channel weights = 2x LDS.128 + 1.
// 3136 = 49*64 -> no bounds checks.
// ---------------------------------------------------------------------------
#define P1 64
__global__ void __launch_bounds__(256) k1_sf(
    const float* __restrict__ x,
    const float* __restrict__ ws,
    const float* __restrict__ bs)
{
    __shared__ float ws_s[CC * 12];           // 12 KB, [c][12] padded
    __shared__ float red[4 * TAPS * P1];      // 9 KB

    const int b     = blockIdx.y;
    const int tilep = blockIdx.x;
    const int tid   = threadIdx.x;
    const int p     = tid & (P1 - 1);
    const int g     = tid >> 6;

#pragma unroll
    for (int i = tid; i < TAPS * CC; i += 256) {
        int n = i >> 8, c = i & 255;
        ws_s[c * 12 + n] = ws[i];
    }
    __syncthreads();

    const int pix = tilep * P1 + p;           // always < HW
    const float* xb = x + ((size_t)b * CC + g * 64) * HW + pix;

    float acc[TAPS];
#pragma unroll
    for (int n = 0; n < TAPS; n++) acc[n] = 0.f;

#pragma unroll 4
    for (int cc = 0; cc < 64; cc++) {
        float xv = __ldg(xb); xb += HW;
        const float* wr = ws_s + (g * 64 + cc) * 12;
        float4 wa = *(const float4*)(wr);
        float4 wb = *(const float4*)(wr + 4);
        float  w8 = wr[8];
        acc[0] = fmaf(xv, wa.x, acc[0]);
        acc[1] = fmaf(xv, wa.y, acc[1]);
        acc[2] = fmaf(xv, wa.z, acc[2]);
        acc[3] = fmaf(xv, wa.w, acc[3]);
        acc[4] = fmaf(xv, wb.x, acc[4]);
        acc[5] = fmaf(xv, wb.y, acc[5]);
        acc[6] = fmaf(xv, wb.z, acc[6]);
        acc[7] = fmaf(xv, wb.w, acc[7]);
        acc[8] = fmaf(xv, w8,   acc[8]);
    }

#pragma unroll
    for (int n = 0; n < TAPS; n++) red[(g * TAPS + n) * P1 + p] = acc[n];
    __syncthreads();

    if (tid < P1) {
        const int pix2 = tilep * P1 + tid;
        float a[TAPS];
        float m = 0.f;
#pragma unroll
        for (int n = 0; n < TAPS; n++) {
            a[n] = red[(0 * TAPS + n) * P1 + tid]
                 + red[(1 * TAPS + n) * P1 + tid]
                 + red[(2 * TAPS + n) * P1 + tid]
                 + red[(3 * TAPS + n) * P1 + tid]
                 + __ldg(bs + n);
            m += a[n];
        }
        m *= (1.f / 9.f);
        float ss = 0.f;
#pragma unroll
        for (int n = 0; n < TAPS; n++) { float d = a[n] - m; ss = fmaf(d, d, ss); }
        float inv = GAIN_OVER_K / (sqrtf(ss * (1.f / 8.f)) + 1e-10f);
#pragma unroll
        for (int n = 0; n < TAPS; n++)
            g_sf[((size_t)b * TAPS + n) * HW + pix2] = (a[n] - m) * inv;
    }
}

// ---------------------------------------------------------------------------
// Kernel 2: MLP -> normalize -> cf. One block per batch.
// Layer1: warp-per-row, coalesced lane reads. Layer2: 128-row contiguous
// chunks of w2 staged in smem via float4 (all coalesced).
// ---------------------------------------------------------------------------
__global__ void __launch_bounds__(256) k2_mlp_cf(
    const float* __restrict__ w1, const float* __restrict__ b1,
    const float* __restrict__ w2, const float* __restrict__ b2,
    const float* __restrict__ fn_std)
{
    __shared__ float pooled_s[CC];            // 1 KB
    __shared__ float y1_s[64];                // 0.25 KB
    __shared__ float w2c[128 * MID];          // 25.5 KB
    __shared__ float y2_s[CKK];               // 9 KB

    const int b    = blockIdx.x;
    const int tid  = threadIdx.x;
    const int warp = tid >> 5;
    const int lane = tid & 31;

    pooled_s[tid] = g_pooled[b * CC + tid];
    __syncthreads();

    // layer 1: 51 rows, one warp per row (rows j, j+8, ...)
    for (int j = warp; j < MID; j += 8) {
        const float* wr = w1 + j * CC;
        float s = 0.f;
#pragma unroll
        for (int k = 0; k < CC / 32; k++)
            s = fmaf(pooled_s[lane + k * 32], __ldg(wr + lane + k * 32), s);
#pragma unroll
        for (int o = 16; o > 0; o >>= 1) s += __shfl_down_sync(0xffffffffu, s, o);
        if (lane == 0) y1_s[j] = fmaxf(s + __ldg(b1 + j), 0.f);
    }
    __syncthreads();

    // layer 2: 2304 rows in 18 chunks of 128 (rows contiguous in gmem)
    for (int ch = 0; ch < 18; ch++) {
        const int r0 = ch * 128;
        __syncthreads();                       // protect w2c reuse
        const float4* src = (const float4*)(w2 + (size_t)r0 * MID);
#pragma unroll
        for (int i = tid; i < 128 * MID / 4; i += 256)
            ((float4*)w2c)[i] = __ldg(src + i);
        __syncthreads();
        if (tid < 128) {
            const int o = r0 + tid;
            float a = __ldg(b2 + o);
            const float* row = w2c + tid * MID;
#pragma unroll
            for (int m = 0; m < MID; m++) a = fmaf(y1_s[m], row[m], a);
            y2_s[o] = a;
        }
    }
    __syncthreads();

    // normalize per channel c = tid over its 9 taps
    const int c = tid;
    float y[TAPS];
    float m = 0.f;
#pragma unroll
    for (int k = 0; k < TAPS; k++) { y[k] = y2_s[c * TAPS + k]; m += y[k]; }
    m *= (1.f / 9.f);
    float ss = 0.f;
#pragma unroll
    for (int k = 0; k < TAPS; k++) { float d = y[k] - m; ss = fmaf(d, d, ss); }
    float inv = 1.f / (sqrtf(ss * (1.f / 8.f)) + 1e-10f);
#pragma unroll
    for (int k = 0; k < TAPS; k++)
        g_cf[(size_t)b * CKK + c * TAPS + k] =
            (y[k] - m) * inv * __ldg(fn_std + c * TAPS + k);
}

// ---------------------------------------------------------------------------
// Kernel 3: DDF combine. 8x56 tile, 16 channels, double-buffered halo,
// channel-invariant index math hoisted, 1 barrier per channel.
// ---------------------------------------------------------------------------
#define K3_CG 16
__global__ void __launch_bounds__(448) k3_ddf(
    const float* __restrict__ x, float* __restrict__ out)
{
    __shared__ float cf_s[K3_CG * TAPS];      // 576 B
    __shared__ float xs[2][10 * 58];          // 4.6 KB

    const int b  = blockIdx.z;
    const int cg = blockIdx.y;
    const int r0 = blockIdx.x * 8;
    const int tx = threadIdx.x;
    const int ty = threadIdx.y;
    const int tid = ty * WW + tx;

    // sf for this thread's pixel: straight to registers
    float sfr[TAPS];
    {
        const float* sp = g_sf + (size_t)b * TAPS * HW + (r0 + ty) * WW + tx;
#pragma unroll
        for (int n = 0; n < TAPS; n++) sfr[n] = __ldg(sp + n * HW);
    }
    if (tid < K3_CG * TAPS)
        cf_s[tid] = g_cf[(size_t)b * CKK + (cg * K3_CG) * TAPS + tid];

    // channel-invariant halo indexing (580 elems, thread covers i0 and maybe i1)
    const int i0 = tid;               // < 580 always
    const int i1 = tid + 448;         // < 580 iff tid < 132
    const int rr0 = i0 / 58, cc0 = i0 % 58;
    const int gr0 = r0 - 1 + rr0, gc0 = cc0 - 1;
    const bool v0 = (gr0 >= 0) && (gr0 < HH) && (gc0 >= 0) && (gc0 < WW);
    const int rr1 = i1 / 58, cc1 = i1 % 58;
    const int gr1 = r0 - 1 + rr1, gc1 = cc1 - 1;
    const bool has1 = (tid < 132);
    const bool v1 = has1 && (gr1 >= 0) && (gr1 < HH) && (gc1 >= 0) && (gc1 < WW);

    const size_t cbase = ((size_t)b * CC + cg * K3_CG) * HW;
    const float* p0 = x + cbase + gr0 * WW + gc0;
    const float* p1 = x + cbase + gr1 * WW + gc1;
    float* po = out + cbase + (r0 + ty) * WW + tx;

    // preload channel 0
    {
        float a0 = v0 ? __ldg(p0) : 0.f;
        float a1 = v1 ? __ldg(p1) : 0.f;
        xs[0][i0] = a0;
        if (has1) xs[0][i1] = a1;
    }
    __syncthreads();

    const float* xr_base0 = &xs[0][ty * 58 + tx];
    const float* xr_base1 = &xs[1][ty * 58 + tx];

#pragma unroll
    for (int g = 0; g < K3_CG; g++) {
        const int cur = g & 1;
        const bool more = (g + 1 < K3_CG);

        // prefetch next channel (LDG in flight during compute)
        float n0 = 0.f, n1 = 0.f;
        if (more) {
            p0 += HW; p1 += HW;
            n0 = v0 ? __ldg(p0) : 0.f;
            n1 = v1 ? __ldg(p1) : 0.f;
        }

        float w[TAPS];
#pragma unroll
        for (int t = 0; t < TAPS; t++) w[t] = cf_s[g * TAPS + t] * sfr[t];

        const float* xr = cur ? xr_base1 : xr_base0;
        float acc = 0.f;
#pragma unroll
        for (int u = 0; u < KK; u++)
#pragma unroll
            for (int v = 0; v < KK; v++)
                acc = fmaf(xr[u * 58 + v], w[u * KK + v], acc);

        *po = acc; po += HW;

        if (more) {
            xs[cur ^ 1][i0] = n0;
            if (has1) xs[cur ^ 1][i1] = n1;
        }
        __syncthreads();
    }
}

// ---------------------------------------------------------------------------
extern "C" void kernel_launch(void* const* d_in, const int* in_sizes, int n_in,
                              void* d_out, int out_size)
{
    const float* x      = (const float*)d_in[0];
    const float* w1     = (const float*)d_in[1];
    const float* b1     = (const float*)d_in[2];
    const float* w2     = (const float*)d_in[3];
    const float* b2     = (const float*)d_in[4];
    const float* ws     = (const float*)d_in[5];
    const float* bs     = (const float*)d_in[6];
    const float* fn_std = (const float*)d_in[7];
    float* out = (float*)d_out;

    dim3 g0(CC, BB);
    k0_pool<<<g0, 128>>>(x);

    dim3 g1(HW / P1, BB);   // 49 x 8
    k1_sf<<<g1, 256>>>(x, ws, bs);

    k2_mlp_cf<<<BB, 256>>>(w1, b1, w2, b2, fn_std);

    dim3 g3(HH / 8, CC / K3_CG, BB);
    dim3 b3(WW, 8);
    k3_ddf<<<g3, b3>>>(x, out);
}

// round 4
// speedup vs baseline: 3.5881x; 1.4937x over previous
#include <cuda_runtime.h>
#include <math.h>

#define BB 8
#define CC 256
#define HH 56
#define WW 56
#define HW (HH*WW)          // 3136
#define KK 3
#define TAPS 9
#define MID 51
#define CKK (CC*TAPS)       // 2304
#define GAIN_OVER_K 0.4714045207910317f   // sqrt(2)/3
#define T1 49               // k1 pixel tiles (49*64 = 3136 exact)

__device__ float g_pp[BB * T1 * CC];   // per-(b,tile) pooled partial sums
__device__ float g_sf[BB * TAPS * HW];
__device__ float g_cf[BB * CKK];

// ---------------------------------------------------------------------------
// Kernel 1: spatial filter + pooled partials (fused; single pass over x).
// Block 256 = 32 p-threads x 8 channel-groups (32 ch each), 2 px per thread.
// Tile = 64 pixels. Warp == one channel group -> butterfly reduce gives the
// full tile sum per channel with no second stage.
// ---------------------------------------------------------------------------
__global__ void __launch_bounds__(256) k1_sf_pool(
    const float* __restrict__ x,
    const float* __restrict__ ws,
    const float* __restrict__ bs)
{
    __shared__ float ws_s[CC * 12];          // 12 KB, transposed [c][12]
    __shared__ float red[8 * TAPS * 64];     // 18 KB
    __shared__ float psum[CC];               // 1 KB

    const int b    = blockIdx.y;
    const int tile = blockIdx.x;
    const int tid  = threadIdx.x;
    const int p    = tid & 31;
    const int g    = tid >> 5;               // warp id == channel group

#pragma unroll
    for (int i = tid; i < TAPS * CC; i += 256) {
        int n = i >> 8, c = i & 255;
        ws_s[c * 12 + n] = ws[i];
    }
    __syncthreads();

    const int pix0 = tile * 64 + p;          // always < HW
    const float* xb = x + ((size_t)b * CC + g * 32) * HW + pix0;

    float acc0[TAPS], acc1[TAPS];
#pragma unroll
    for (int n = 0; n < TAPS; n++) { acc0[n] = 0.f; acc1[n] = 0.f; }

#pragma unroll 4
    for (int cc = 0; cc < 32; cc++) {
        float xv0 = __ldg(xb);
        float xv1 = __ldg(xb + 32);
        xb += HW;
        const float* wr = ws_s + (g * 32 + cc) * 12;
        float4 wa = *(const float4*)(wr);
        float4 wb = *(const float4*)(wr + 4);
        float  w8 = wr[8];
        acc0[0] = fmaf(xv0, wa.x, acc0[0]);  acc1[0] = fmaf(xv1, wa.x, acc1[0]);
        acc0[1] = fmaf(xv0, wa.y, acc0[1]);  acc1[1] = fmaf(xv1, wa.y, acc1[1]);
        acc0[2] = fmaf(xv0, wa.z, acc0[2]);  acc1[2] = fmaf(xv1, wa.z, acc1[2]);
        acc0[3] = fmaf(xv0, wa.w, acc0[3]);  acc1[3] = fmaf(xv1, wa.w, acc1[3]);
        acc0[4] = fmaf(xv0, wb.x, acc0[4]);  acc1[4] = fmaf(xv1, wb.x, acc1[4]);
        acc0[5] = fmaf(xv0, wb.y, acc0[5]);  acc1[5] = fmaf(xv1, wb.y, acc1[5]);
        acc0[6] = fmaf(xv0, wb.z, acc0[6]);  acc1[6] = fmaf(xv1, wb.z, acc1[6]);
        acc0[7] = fmaf(xv0, wb.w, acc0[7]);  acc1[7] = fmaf(xv1, wb.w, acc1[7]);
        acc0[8] = fmaf(xv0, w8,   acc0[8]);  acc1[8] = fmaf(xv1, w8,   acc1[8]);

        // pooled partial: sum of 64 tile pixels for this channel
        float s = xv0 + xv1;
#pragma unroll
        for (int o = 16; o > 0; o >>= 1) s += __shfl_xor_sync(0xffffffffu, s, o);
        if (p == 0) psum[g * 32 + cc] = s;
    }

#pragma unroll
    for (int n = 0; n < TAPS; n++) {
        red[(g * TAPS + n) * 64 + p]      = acc0[n];
        red[(g * TAPS + n) * 64 + p + 32] = acc1[n];
    }
    __syncthreads();

    g_pp[((size_t)b * T1 + tile) * CC + tid] = psum[tid];

    if (tid < 64) {
        float a[TAPS];
        float m = 0.f;
#pragma unroll
        for (int n = 0; n < TAPS; n++) {
            float s = 0.f;
#pragma unroll
            for (int gg = 0; gg < 8; gg++) s += red[(gg * TAPS + n) * 64 + tid];
            a[n] = s + __ldg(bs + n);
            m += a[n];
        }
        m *= (1.f / 9.f);
        float ss = 0.f;
#pragma unroll
        for (int n = 0; n < TAPS; n++) { float d = a[n] - m; ss = fmaf(d, d, ss); }
        float inv = GAIN_OVER_K / (sqrtf(ss * (1.f / 8.f)) + 1e-10f);
        const int pix = tile * 64 + tid;
#pragma unroll
        for (int n = 0; n < TAPS; n++)
            g_sf[((size_t)b * TAPS + n) * HW + pix] = (a[n] - m) * inv;
    }
}

// ---------------------------------------------------------------------------
// Kernel 2: pooled finish + MLP + per-channel normalize -> cf.
// Grid (16 chunks, 8 batch): each block owns 16 channels = 144 w2 rows.
// Layer 1 recomputed per block (trivial).
// ---------------------------------------------------------------------------
__global__ void __launch_bounds__(256) k2_mlp_cf(
    const float* __restrict__ w1, const float* __restrict__ b1,
    const float* __restrict__ w2, const float* __restrict__ b2,
    const float* __restrict__ fn_std)
{
    __shared__ float pooled_s[CC];
    __shared__ float y1_s[52];
    __shared__ float w2c[144 * MID];          // 28.7 KB
    __shared__ float y2_s[144];

    const int cg   = blockIdx.x;              // channel chunk (16 ch)
    const int b    = blockIdx.y;
    const int tid  = threadIdx.x;
    const int warp = tid >> 5;
    const int lane = tid & 31;

    // pooled mean
    {
        float s = 0.f;
#pragma unroll
        for (int t = 0; t < T1; t++) s += g_pp[((size_t)b * T1 + t) * CC + tid];
        pooled_s[tid] = s * (1.f / (float)HW);
    }

    // stage w2 chunk (rows cg*144 .. +144), fully coalesced float4
    {
        const float4* src = (const float4*)(w2 + (size_t)cg * 144 * MID);
#pragma unroll
        for (int i = tid; i < 144 * MID / 4; i += 256)
            ((float4*)w2c)[i] = __ldg(src + i);
    }
    __syncthreads();

    // layer 1: warp per row
    for (int j = warp; j < MID; j += 8) {
        const float* wr = w1 + j * CC;
        float s = 0.f;
#pragma unroll
        for (int k = 0; k < CC / 32; k++)
            s = fmaf(pooled_s[lane + k * 32], __ldg(wr + lane + k * 32), s);
#pragma unroll
        for (int o = 16; o > 0; o >>= 1) s += __shfl_xor_sync(0xffffffffu, s, o);
        if (lane == 0) y1_s[j] = fmaxf(s + __ldg(b1 + j), 0.f);
    }
    __syncthreads();

    // layer 2: 144 rows
    if (tid < 144) {
        const int r = cg * 144 + tid;
        float a = __ldg(b2 + r);
        const float* row = w2c + tid * MID;
#pragma unroll
        for (int m = 0; m < MID; m++) a = fmaf(y1_s[m], row[m], a);
        y2_s[tid] = a;
    }
    __syncthreads();

    // normalize 16 channels
    if (tid < 16) {
        const int c = cg * 16 + tid;
        float y[TAPS];
        float m = 0.f;
#pragma unroll
        for (int k = 0; k < TAPS; k++) { y[k] = y2_s[tid * TAPS + k]; m += y[k]; }
        m *= (1.f / 9.f);
        float ss = 0.f;
#pragma unroll
        for (int k = 0; k < TAPS; k++) { float d = y[k] - m; ss = fmaf(d, d, ss); }
        float inv = 1.f / (sqrtf(ss * (1.f / 8.f)) + 1e-10f);
#pragma unroll
        for (int k = 0; k < TAPS; k++)
            g_cf[(size_t)b * CKK + c * TAPS + k] =
                (y[k] - m) * inv * __ldg(fn_std + c * TAPS + k);
    }
}

// ---------------------------------------------------------------------------
// Kernel 3: DDF combine. 8x56 tile, ALL 16 channels' halos preloaded into
// smem (one barrier total), 2 vertical outputs per thread.
// Block (56,4) = 224 thr. Grid (7 row-tiles, 16 cgroups, 8 batch).
// ---------------------------------------------------------------------------
#define K3_CG 16
#define HALO 580                  // 10*58
__global__ void __launch_bounds__(224) k3_ddf(
    const float* __restrict__ x, float* __restrict__ out)
{
    __shared__ float xh[K3_CG * HALO];       // 37.1 KB
    __shared__ float cf_s[K3_CG * TAPS];

    const int b  = blockIdx.z;
    const int cg = blockIdx.y;
    const int r0 = blockIdx.x * 8;
    const int tx = threadIdx.x;
    const int ty = threadIdx.y;              // 0..3
    const int tid = ty * WW + tx;

    // sf for this thread's 2 output pixels -> registers
    float sfr0[TAPS], sfr1[TAPS];
    {
        const float* sp = g_sf + (size_t)b * TAPS * HW + (r0 + 2 * ty) * WW + tx;
#pragma unroll
        for (int n = 0; n < TAPS; n++) {
            sfr0[n] = __ldg(sp + n * HW);
            sfr1[n] = __ldg(sp + n * HW + WW);
        }
    }
    if (tid < K3_CG * TAPS)
        cf_s[tid] = g_cf[(size_t)b * CKK + (cg * K3_CG) * TAPS + tid];

    // channel-invariant halo indexing: 3 slots per thread (224*3 >= 580)
    int  idx[3]; const float* ptr[3]; bool vld[3], has[3];
#pragma unroll
    for (int s = 0; s < 3; s++) {
        int i = tid + s * 224;
        has[s] = (i < HALO);
        int ii = has[s] ? i : 0;
        int rr = ii / 58, cc2 = ii % 58;
        int gr = r0 - 1 + rr, gc = cc2 - 1;
        vld[s] = has[s] && (gr >= 0) && (gr < HH) && (gc >= 0) && (gc < WW);
        idx[s] = ii;
        ptr[s] = x + ((size_t)b * CC + cg * K3_CG) * HW + gr * WW + gc;
    }

    // load all 16 channels' halos (48 LDG in flight, one barrier)
#pragma unroll
    for (int g = 0; g < K3_CG; g++) {
#pragma unroll
        for (int s = 0; s < 3; s++) {
            float v = vld[s] ? __ldg(ptr[s] + (size_t)g * HW) : 0.f;
            if (has[s]) xh[g * HALO + idx[s]] = v;
        }
    }
    __syncthreads();

    const size_t cbase = ((size_t)b * CC + cg * K3_CG) * HW;
    float* po0 = out + cbase + (r0 + 2 * ty) * WW + tx;

#pragma unroll
    for (int g = 0; g < K3_CG; g++) {
        float w0[TAPS], w1[TAPS];
#pragma unroll
        for (int t = 0; t < TAPS; t++) {
            float c = cf_s[g * TAPS + t];
            w0[t] = c * sfr0[t];
            w1[t] = c * sfr1[t];
        }
        const float* xr = xh + g * HALO + (2 * ty) * 58 + tx;
        float acc0 = 0.f, acc1 = 0.f;
#pragma unroll
        for (int u = 0; u < KK; u++) {
#pragma unroll
            for (int v = 0; v < KK; v++) {
                float xa = xr[u * 58 + v];
                float xb2 = xr[(u + 1) * 58 + v];
                acc0 = fmaf(xa,  w0[u * KK + v], acc0);
                acc1 = fmaf(xb2, w1[u * KK + v], acc1);
            }
        }
        po0[0]  = acc0;
        po0[WW] = acc1;
        po0 += HW;
    }
}

// ---------------------------------------------------------------------------
extern "C" void kernel_launch(void* const* d_in, const int* in_sizes, int n_in,
                              void* d_out, int out_size)
{
    const float* x      = (const float*)d_in[0];
    const float* w1     = (const float*)d_in[1];
    const float* b1     = (const float*)d_in[2];
    const float* w2     = (const float*)d_in[3];
    const float* b2     = (const float*)d_in[4];
    const float* ws     = (const float*)d_in[5];
    const float* bs     = (const float*)d_in[6];
    const float* fn_std = (const float*)d_in[7];
    float* out = (float*)d_out;

    dim3 g1(T1, BB);                 // 49 x 8
    k1_sf_pool<<<g1, 256>>>(x, ws, bs);

    dim3 g2(16, BB);                 // 16 chunks x 8 batch
    k2_mlp_cf<<<g2, 256>>>(w1, b1, w2, b2, fn_std);

    dim3 g3(HH / 8, CC / K3_CG, BB);
    dim3 b3(WW, 4);
    k3_ddf<<<g3, b3>>>(x, out);
}